// round 15
// baseline (speedup 1.0000x reference)
#include <cuda_runtime.h>
#include <cuda_fp16.h>
#include <cstdint>
#include <cstddef>

// ---------------- problem constants ----------------
#define D_MODEL   1024
#define D_PROJ    256
#define MTILE     64                   // rows per CTA
#define NCHUNKS   32                   // K chunks of 32
#define EPS1      1e-5f

// smem map (bytes): same as R14
#define SA_OFF    8192
#define SB_OFF    24576
#define A_STAGE   4096u
#define B_STAGE   16384u
#define SMEM_BYTES 90112               // 2 CTAs/SM

// ---------------- device scratch ----------------
__device__ __half g_Wp[D_PROJ * D_MODEL];   // fp16 rna, gamma1-scaled, natural k
__device__ float  g_u[D_PROJ];
__device__ float  g_v[D_PROJ];

// ---------------- helpers ----------------
static __device__ __forceinline__ uint32_t smem_u32(const void* p) {
    uint32_t a;
    asm("{ .reg .u64 t; cvta.to.shared.u64 t, %1; cvt.u32.u64 %0, t; }" : "=r"(a) : "l"(p));
    return a;
}

// 16B-group swizzle over 64B rows: sw2(r) = (r + (r>>2)) & 3  (invariant +16/+32)
static __device__ __forceinline__ uint32_t sw2(int r) {
    return (uint32_t)((r + (r >> 2)) & 3);
}

#define CP_COMMIT() asm volatile("cp.async.commit_group;" ::: "memory")
#define CP_WAIT2()  asm volatile("cp.async.wait_group 2;" ::: "memory")

#define CVT2(w, hi, lo)                                                       \
    asm("cvt.rn.f16x2.f32 %0, %1, %2;" : "=r"(w) : "f"(hi), "f"(lo))

#define LDM4(r0, r1, r2, r3, addr)                                            \
    asm volatile("ldmatrix.sync.aligned.m8n8.x4.shared.b16 {%0,%1,%2,%3}, [%4];" \
        : "=r"(r0), "=r"(r1), "=r"(r2), "=r"(r3) : "r"(addr))

#define MMA_F16(d, a0, a1, a2, a3, b0, b1)                                    \
    asm volatile("mma.sync.aligned.m16n8k16.row.col.f32.f16.f16.f32 "         \
        "{%0,%1,%2,%3}, {%4,%5,%6,%7}, {%8,%9}, {%0,%1,%2,%3};"               \
        : "+f"((d)[0]), "+f"((d)[1]), "+f"((d)[2]), "+f"((d)[3])              \
        : "r"(a0), "r"(a1), "r"(a2), "r"(a3), "r"(b0), "r"(b1))

#define STS128(addr, c0, c1, c2, c3)                                          \
    asm volatile("st.shared.v4.b32 [%0], {%1,%2,%3,%4};"                      \
        :: "r"(addr), "r"(c0), "r"(c1), "r"(c2), "r"(c3))

// ---------------- prep ----------------
__global__ void __launch_bounds__(256) prep_kernel(
    const float* __restrict__ W, const float* __restrict__ g1,
    const float* __restrict__ b1, const float* __restrict__ bias)
{
    __shared__ float ru[8], rv[8];
    int p = blockIdx.x, t = threadIdx.x;
    const float* wrow = W + (size_t)p * D_MODEL;
    float u = 0.f, v = 0.f;
#pragma unroll
    for (int i = 0; i < 4; ++i) {
        int d = t + i * 256;
        float w  = wrow[d];
        float gw = g1[d] * w;
        __half h = __float2half_rn(gw);
        u += __half2float(h);
        v += b1[d] * w;
        g_Wp[(size_t)p * D_MODEL + d] = h;
    }
#pragma unroll
    for (int o = 16; o > 0; o >>= 1) {
        u += __shfl_xor_sync(0xFFFFFFFFu, u, o);
        v += __shfl_xor_sync(0xFFFFFFFFu, v, o);
    }
    if ((t & 31) == 0) { ru[t >> 5] = u; rv[t >> 5] = v; }
    __syncthreads();
    if (t == 0) {
        float uu = 0.f, vv = 0.f;
#pragma unroll
        for (int i = 0; i < 8; ++i) { uu += ru[i]; vv += rv[i]; }
        g_u[p] = uu;
        g_v[p] = vv + bias[p];
    }
}

// ---------------- main fused kernel: 128 thr, warp tile 64x64, 2 CTAs/SM ----------------
__global__ void __launch_bounds__(128, 2) fused_kernel(
    const float* __restrict__ x,
    const float* __restrict__ g2v, const float* __restrict__ b2v,
    float* __restrict__ out)
{
    extern __shared__ char smem[];
    const uint32_t sb = smem_u32(smem);
    const int tid  = threadIdx.x;
    const int lane = tid & 31;
    const int wn   = tid >> 5;          // warp 0..3 -> n slice (64 cols)
    const int qt   = lane & 3;
    const int qr   = lane >> 2;

    float* suv = (float*)smem;          // u, v, g2, b2
#pragma unroll
    for (int j = 0; j < 2; ++j) {
        suv[tid + j * 128]       = g_u[tid + j * 128];
        suv[256 + tid + j * 128] = g_v[tid + j * 128];
        suv[512 + tid + j * 128] = g2v[tid + j * 128];
        suv[768 + tid + j * 128] = b2v[tid + j * 128];
    }

    const size_t row0 = (size_t)blockIdx.x * MTILE;
    const uint32_t sA = sb + SA_OFF;
    const uint32_t sB = sb + SB_OFF;

    // ---- A loader: thread -> rows ar, ar+32, fp32 quarter aq (32B each) ----
    const int ar = tid >> 2, aq = tid & 3;
    const char* a_g = (const char*)x + (row0 + (size_t)ar) * 4096 + (size_t)aq * 32;
    const uint32_t a_sts = sA + (uint32_t)ar * 64 + ((((uint32_t)aq) ^ sw2(ar)) << 4);

    // ---- B loader: thread -> rows brb+32i (i<8), group bq2 ----
    const int brb = tid >> 2, bq2 = tid & 3;
    const uint32_t b_dst = sB + (uint32_t)brb * 64 + ((((uint32_t)bq2) ^ sw2(brb)) << 4);
    const char* b_src = (const char*)g_Wp + (size_t)brb * 2048 + (size_t)bq2 * 16;

    // ---- ldmatrix lane addresses (stage 0, k-step 0); k-step1 = XOR 32 ----
    uint32_t aAd;                        // mt tiles via +1024*mt (sw2 invariant +16)
    {
        int R = (lane & 7) + ((lane >> 3) & 1) * 8;
        uint32_t g = (uint32_t)((lane >> 4) & 1);
        aAd = sA + (uint32_t)R * 64 + ((g ^ sw2(R)) << 4);
    }
    uint32_t bAd[4];
#pragma unroll
    for (int o = 0; o < 4; ++o) {
        int nt = 2 * o + ((lane >> 4) & 1);
        int N  = wn * 64 + nt * 8 + (lane & 7);
        uint32_t g = (uint32_t)((lane >> 3) & 1);
        bAd[o] = sB + (uint32_t)N * 64 + ((g ^ sw2(N)) << 4);
    }

    float acc[4][8][4];
#pragma unroll
    for (int a = 0; a < 4; ++a)
#pragma unroll
        for (int b = 0; b < 8; ++b)
#pragma unroll
            for (int c = 0; c < 4; ++c) acc[a][b][c] = 0.f;

    float s1a = 0.f, s2a = 0.f, s1b = 0.f, s2b = 0.f;
    float4 af0, af1, af2, af3;           // rows ar (af0,af1), ar+32 (af2,af3)

#define LDGA(KC)                                                               \
    do {                                                                       \
        const float4* _p = (const float4*)(a_g + (size_t)(KC) * 128);          \
        af0 = _p[0]; af1 = _p[1];                                              \
        const float4* _q = (const float4*)(a_g + 131072 + (size_t)(KC) * 128); \
        af2 = _q[0]; af3 = _q[1];                                              \
    } while (0)

#define STSA(SOFF)                                                             \
    do {                                                                       \
        s1a += ((af0.x + af0.y) + (af0.z + af0.w))                             \
             + ((af1.x + af1.y) + (af1.z + af1.w));                            \
        s2a += ((af0.x * af0.x + af0.y * af0.y) + (af0.z * af0.z + af0.w * af0.w)) \
             + ((af1.x * af1.x + af1.y * af1.y) + (af1.z * af1.z + af1.w * af1.w)); \
        s1b += ((af2.x + af2.y) + (af2.z + af2.w))                             \
             + ((af3.x + af3.y) + (af3.z + af3.w));                            \
        s2b += ((af2.x * af2.x + af2.y * af2.y) + (af2.z * af2.z + af2.w * af2.w)) \
             + ((af3.x * af3.x + af3.y * af3.y) + (af3.z * af3.z + af3.w * af3.w)); \
        uint32_t w0, w1, w2, w3;                                               \
        CVT2(w0, af0.y, af0.x); CVT2(w1, af0.w, af0.z);                        \
        CVT2(w2, af1.y, af1.x); CVT2(w3, af1.w, af1.z);                        \
        STS128(a_sts + (SOFF), w0, w1, w2, w3);                                \
        CVT2(w0, af2.y, af2.x); CVT2(w1, af2.w, af2.z);                        \
        CVT2(w2, af3.y, af3.x); CVT2(w3, af3.w, af3.z);                        \
        STS128(a_sts + (SOFF) + 2048u, w0, w1, w2, w3);                        \
    } while (0)

#define LOADB(KC, SOFF)                                                        \
    do {                                                                       \
        const char* _b = b_src + (size_t)(KC) * 64;                            \
        _Pragma("unroll")                                                      \
        for (int i = 0; i < 8; ++i)                                            \
            asm volatile("cp.async.cg.shared.global [%0], [%1], 16;"           \
                :: "r"(b_dst + (SOFF) + (uint32_t)i * 2048),                   \
                   "l"(_b + (size_t)i * 65536));                               \
    } while (0)

#define COMPUTE(SOFFA, SOFFB)                                                  \
    do {                                                                       \
        _Pragma("unroll")                                                      \
        for (int stk = 0; stk < 2; ++stk) {                                    \
            const uint32_t xr = (uint32_t)stk << 5;                            \
            uint32_t bfr[4][4];                                                \
            _Pragma("unroll")                                                  \
            for (int o = 0; o < 4; ++o)                                        \
                LDM4(bfr[o][0], bfr[o][1], bfr[o][2], bfr[o][3],               \
                     (bAd[o] + (SOFFB)) ^ xr);                                 \
            _Pragma("unroll")                                                  \
            for (int mt = 0; mt < 4; ++mt) {                                   \
                uint32_t a0, a1, a2, a3;                                       \
                LDM4(a0, a1, a2, a3,                                           \
                     (aAd + (SOFFA) + (uint32_t)mt * 1024) ^ xr);              \
                _Pragma("unroll")                                              \
                for (int o = 0; o < 4; ++o) {                                  \
                    MMA_F16(acc[mt][2 * o],     a0, a1, a2, a3,                \
                            bfr[o][0], bfr[o][1]);                             \
                    MMA_F16(acc[mt][2 * o + 1], a0, a1, a2, a3,                \
                            bfr[o][2], bfr[o][3]);                             \
                }                                                              \
            }                                                                  \
        }                                                                      \
    } while (0)

    // ---------------- prologue ----------------
    LDGA(0);
    STSA(0u);
    LDGA(1);
    LOADB(0, 0u);            CP_COMMIT();
    LOADB(1, B_STAGE);       CP_COMMIT();
    LOADB(2, 2 * B_STAGE);   CP_COMMIT();

    // ---------------- mainloop: 4-stage, one sync per chunk ----------------
#pragma unroll 1
    for (int kc = 0; kc < NCHUNKS; ++kc) {
        CP_WAIT2();                                 // B(kc) resident
        if (kc + 1 < NCHUNKS) STSA((uint32_t)((kc + 1) & 3) * A_STAGE);
        __syncthreads();
        if (kc + 3 < NCHUNKS) LOADB(kc + 3, (uint32_t)((kc + 3) & 3) * B_STAGE);
        CP_COMMIT();
        if (kc + 2 < NCHUNKS) LDGA(kc + 2);
        COMPUTE((uint32_t)(kc & 3) * A_STAGE, (uint32_t)(kc & 3) * B_STAGE);
    }

    // ---------------- LN1 finalize ----------------
    float* s1p = (float*)(smem + 4096);             // [256]
    float* s2p = (float*)(smem + 5120);             // [256]
    float* ca  = (float*)(smem + 6144);             // [64]
    float* cb  = ca + 64;                           // [64]
    float* rowacc = (float*)(smem + SA_OFF);        // [64][4][2]
    float* mu2a = (float*)(smem + SA_OFF + 2048);
    float* rs2a = mu2a + 64;

    __syncthreads();
    s1p[tid] = s1a; s1p[tid + 128] = s1b;
    s2p[tid] = s2a; s2p[tid + 128] = s2b;
    __syncthreads();

    if (tid < 64) {
        int off = ((tid >> 5) * 128) + (tid & 31) * 4;   // rows 0-31 low, 32-63 high
        float a = (s1p[off] + s1p[off + 1]) + (s1p[off + 2] + s1p[off + 3]);
        float b = (s2p[off] + s2p[off + 1]) + (s2p[off + 2] + s2p[off + 3]);
        float mu  = a * (1.0f / (float)D_MODEL);
        float var = fmaf(-mu, mu, b * (1.0f / (float)D_MODEL));
        float rs  = rsqrtf(var + EPS1);
        ca[tid] = rs;
        cb[tid] = -mu * rs;
    }
    rowacc[tid] = 0.f; rowacc[tid + 128] = 0.f;
    rowacc[tid + 256] = 0.f; rowacc[tid + 384] = 0.f;
    __syncthreads();

    // ---------------- h = ca*acc + cb*u + v; LN2 partial sums ----------------
#pragma unroll
    for (int mt = 0; mt < 4; ++mt) {
#pragma unroll
        for (int b = 0; b < 2; ++b) {
            int rr = mt * 16 + qr + 8 * b;
            float cav = ca[rr], cbv = cb[rr];
            float t1 = 0.f, t2 = 0.f;
#pragma unroll
            for (int nt = 0; nt < 8; ++nt) {
                int p0 = wn * 64 + nt * 8 + 2 * qt;
                float h0 = fmaf(cav, acc[mt][nt][2 * b],     fmaf(cbv, suv[p0],     suv[256 + p0]));
                float h1 = fmaf(cav, acc[mt][nt][2 * b + 1], fmaf(cbv, suv[p0 + 1], suv[256 + p0 + 1]));
                acc[mt][nt][2 * b]     = h0;
                acc[mt][nt][2 * b + 1] = h1;
                t1 += h0 + h1;
                t2 += h0 * h0 + h1 * h1;
            }
            t1 += __shfl_xor_sync(0xFFFFFFFFu, t1, 1);
            t2 += __shfl_xor_sync(0xFFFFFFFFu, t2, 1);
            t1 += __shfl_xor_sync(0xFFFFFFFFu, t1, 2);
            t2 += __shfl_xor_sync(0xFFFFFFFFu, t2, 2);
            if (qt == 0) {
                rowacc[(rr * 4 + wn) * 2]     = t1;
                rowacc[(rr * 4 + wn) * 2 + 1] = t2;
            }
        }
    }
    __syncthreads();

    if (tid < 64) {
        float t1 = 0.f, t2 = 0.f;
#pragma unroll
        for (int w = 0; w < 4; ++w) {
            t1 += rowacc[(tid * 4 + w) * 2];
            t2 += rowacc[(tid * 4 + w) * 2 + 1];
        }
        float mu  = t1 * (1.0f / (float)D_PROJ);
        float var = fmaf(-mu, mu, t2 * (1.0f / (float)D_PROJ));
        mu2a[tid] = mu;
        rs2a[tid] = rsqrtf(var + EPS1);
    }
    __syncthreads();

    // ---------------- normalize + store ----------------
    float* outp = out + row0 * D_PROJ;
#pragma unroll
    for (int mt = 0; mt < 4; ++mt) {
#pragma unroll
        for (int b = 0; b < 2; ++b) {
            int rr = mt * 16 + qr + 8 * b;
            float mu = mu2a[rr], rs = rs2a[rr];
#pragma unroll
            for (int nt = 0; nt < 8; ++nt) {
                int p0 = wn * 64 + nt * 8 + 2 * qt;
                float o0 = fmaf((acc[mt][nt][2 * b]     - mu) * rs, suv[512 + p0],     suv[768 + p0]);
                float o1 = fmaf((acc[mt][nt][2 * b + 1] - mu) * rs, suv[512 + p0 + 1], suv[768 + p0 + 1]);
                float2 o = make_float2(o0, o1);
                *(float2*)(outp + (size_t)rr * D_PROJ + p0) = o;
            }
        }
    }
#undef LDGA
#undef STSA
#undef LOADB
#undef COMPUTE
}

// ---------------- launch ----------------
extern "C" void kernel_launch(void* const* d_in, const int* in_sizes, int n_in,
                              void* d_out, int out_size)
{
    const float* x    = (const float*)d_in[0];
    const float* g1   = (const float*)d_in[1];
    const float* b1   = (const float*)d_in[2];
    const float* W    = (const float*)d_in[3];
    const float* bias = (const float*)d_in[4];
    const float* g2   = (const float*)d_in[5];
    const float* b2   = (const float*)d_in[6];
    float* out = (float*)d_out;

    int n_tok = in_sizes[0] / D_MODEL;          // 65536
    int grid  = n_tok / MTILE;                  // 1024

    prep_kernel<<<D_PROJ, 256>>>(W, g1, b1, bias);

    cudaFuncSetAttribute(fused_kernel, cudaFuncAttributeMaxDynamicSharedMemorySize, SMEM_BYTES);
    fused_kernel<<<grid, 128, SMEM_BYTES>>>(x, g2, b2, out);
}

// round 16
// speedup vs baseline: 1.2250x; 1.2250x over previous
#include <cuda_runtime.h>
#include <cuda_fp16.h>
#include <cstdint>
#include <cstddef>

// ---------------- problem constants ----------------
#define D_MODEL   1024
#define D_PROJ    256
#define MTILE     64                   // rows per CTA
#define NCHUNKS   32                   // K chunks of 32
#define EPS1      1e-5f

// smem map (bytes): identical to R14
#define SA_OFF    8192
#define SB_OFF    24576
#define A_STAGE   4096u
#define B_STAGE   16384u
#define SMEM_BYTES 90112               // 2 CTAs/SM

// ---------------- device scratch ----------------
__device__ __half g_Wp[D_PROJ * D_MODEL];   // fp16 rna, gamma1-scaled, natural k
__device__ float  g_u[D_PROJ];
__device__ float  g_v[D_PROJ];

// ---------------- helpers ----------------
static __device__ __forceinline__ uint32_t smem_u32(const void* p) {
    uint32_t a;
    asm("{ .reg .u64 t; cvta.to.shared.u64 t, %1; cvt.u32.u64 %0, t; }" : "=r"(a) : "l"(p));
    return a;
}

// 16B-group swizzle over 64B rows: sw2(r) = (r + (r>>2)) & 3
static __device__ __forceinline__ uint32_t sw2(int r) {
    return (uint32_t)((r + (r >> 2)) & 3);
}

#define CP_COMMIT() asm volatile("cp.async.commit_group;" ::: "memory")
#define CP_WAIT0()  asm volatile("cp.async.wait_group 0;" ::: "memory")

#define CVT2(w, hi, lo)                                                       \
    asm("cvt.rn.f16x2.f32 %0, %1, %2;" : "=r"(w) : "f"(hi), "f"(lo))

#define LDM4(r0, r1, r2, r3, addr)                                            \
    asm volatile("ldmatrix.sync.aligned.m8n8.x4.shared.b16 {%0,%1,%2,%3}, [%4];" \
        : "=r"(r0), "=r"(r1), "=r"(r2), "=r"(r3) : "r"(addr))

#define MMA_F16(d, a0, a1, a2, a3, b0, b1)                                    \
    asm volatile("mma.sync.aligned.m16n8k16.row.col.f32.f16.f16.f32 "         \
        "{%0,%1,%2,%3}, {%4,%5,%6,%7}, {%8,%9}, {%0,%1,%2,%3};"               \
        : "+f"((d)[0]), "+f"((d)[1]), "+f"((d)[2]), "+f"((d)[3])              \
        : "r"(a0), "r"(a1), "r"(a2), "r"(a3), "r"(b0), "r"(b1))

#define STS128(addr, c0, c1, c2, c3)                                          \
    asm volatile("st.shared.v4.b32 [%0], {%1,%2,%3,%4};"                      \
        :: "r"(addr), "r"(c0), "r"(c1), "r"(c2), "r"(c3))

// ---------------- prep: W' = g1.*W (fp16-rna), natural layout; u, v ----------------
__global__ void __launch_bounds__(256) prep_kernel(
    const float* __restrict__ W, const float* __restrict__ g1,
    const float* __restrict__ b1, const float* __restrict__ bias)
{
    __shared__ float ru[8], rv[8];
    int p = blockIdx.x, t = threadIdx.x;
    const float* wrow = W + (size_t)p * D_MODEL;
    float u = 0.f, v = 0.f;
#pragma unroll
    for (int i = 0; i < 4; ++i) {
        int d = t + i * 256;
        float w  = wrow[d];
        float gw = g1[d] * w;
        __half h = __float2half_rn(gw);
        u += __half2float(h);
        v += b1[d] * w;
        g_Wp[(size_t)p * D_MODEL + d] = h;
    }
#pragma unroll
    for (int o = 16; o > 0; o >>= 1) {
        u += __shfl_xor_sync(0xFFFFFFFFu, u, o);
        v += __shfl_xor_sync(0xFFFFFFFFu, v, o);
    }
    if ((t & 31) == 0) { ru[t >> 5] = u; rv[t >> 5] = v; }
    __syncthreads();
    if (t == 0) {
        float uu = 0.f, vv = 0.f;
#pragma unroll
        for (int i = 0; i < 8; ++i) { uu += ru[i]; vv += rv[i]; }
        g_u[p] = uu;
        g_v[p] = vv + bias[p];
    }
}

// ---------------- main fused kernel: fp16 MMA, M=64, 2 CTAs/SM, paired chunks ----------------
__global__ void __launch_bounds__(256, 2) fused_kernel(
    const float* __restrict__ x,
    const float* __restrict__ g2v, const float* __restrict__ b2v,
    float* __restrict__ out)
{
    extern __shared__ char smem[];
    const uint32_t sb = smem_u32(smem);
    const int tid  = threadIdx.x;
    const int lane = tid & 31;
    const int wid  = tid >> 5;
    const int wm   = wid >> 2;          // 0..1
    const int wn   = wid & 3;           // 0..3
    const int qt   = lane & 3;
    const int qr   = lane >> 2;

    float* suv = (float*)smem;          // u, v, g2, b2
    suv[tid]       = g_u[tid];
    suv[256 + tid] = g_v[tid];
    suv[512 + tid] = g2v[tid];
    suv[768 + tid] = b2v[tid];

    const size_t row0 = (size_t)blockIdx.x * MTILE;
    const uint32_t sA = sb + SA_OFF;
    const uint32_t sB = sb + SB_OFF;

    // ---- A loader (LDG fp32 -> stats -> cvt -> STS fp16) ----
    const int arow = tid >> 2, aq = tid & 3;
    const char* a_gbase = (const char*)x + (row0 + (size_t)arow) * 4096 + (size_t)aq * 32;
    const uint32_t a_sts = sA + (uint32_t)arow * 64 + ((((uint32_t)aq) ^ sw2(arow)) << 4);

    // ---- B loader (cp.async 16B x4 per chunk) ----
    const int btp = tid >> 2, bq = tid & 3;
    const uint32_t b_dst = sB + (uint32_t)btp * 64 + ((((uint32_t)bq) ^ sw2(btp)) << 4);
    const char* b_src = (const char*)g_Wp + (size_t)btp * 2048 + (size_t)bq * 16;

    // ---- ldmatrix lane addresses ----
    uint32_t aAd[2];
#pragma unroll
    for (int mt = 0; mt < 2; ++mt) {
        int R = wm * 32 + mt * 16 + (lane & 7) + ((lane >> 3) & 1) * 8;
        uint32_t g = (uint32_t)((lane >> 4) & 1);
        aAd[mt] = sA + (uint32_t)R * 64 + ((g ^ sw2(R)) << 4);
    }
    uint32_t bAd[4];
#pragma unroll
    for (int o = 0; o < 4; ++o) {
        int nt = 2 * o + ((lane >> 4) & 1);
        int N  = wn * 64 + nt * 8 + (lane & 7);
        uint32_t g = (uint32_t)((lane >> 3) & 1);
        bAd[o] = sB + (uint32_t)N * 64 + ((g ^ sw2(N)) << 4);
    }

    float acc[2][8][4];
#pragma unroll
    for (int a = 0; a < 2; ++a)
#pragma unroll
        for (int b = 0; b < 8; ++b)
#pragma unroll
            for (int c = 0; c < 4; ++c) acc[a][b][c] = 0.f;

    float s1 = 0.f, s2 = 0.f;
    float4 aA0, aA1, aB0, aB1;          // two in-flight A chunks (sets A and B)

#define LDGA_A(KC)                                                             \
    do {                                                                       \
        const float4* _p = (const float4*)(a_gbase + (size_t)(KC) * 128);      \
        aA0 = _p[0]; aA1 = _p[1];                                              \
    } while (0)

#define LDGA_B(KC)                                                             \
    do {                                                                       \
        const float4* _p = (const float4*)(a_gbase + (size_t)(KC) * 128);      \
        aB0 = _p[0]; aB1 = _p[1];                                              \
    } while (0)

#define STSA_SET(F0, F1, SOFF)                                                 \
    do {                                                                       \
        s1 += ((F0.x + F0.y) + (F0.z + F0.w))                                  \
            + ((F1.x + F1.y) + (F1.z + F1.w));                                 \
        s2 += ((F0.x * F0.x + F0.y * F0.y) + (F0.z * F0.z + F0.w * F0.w))      \
            + ((F1.x * F1.x + F1.y * F1.y) + (F1.z * F1.z + F1.w * F1.w));     \
        uint32_t w0, w1, w2, w3;                                               \
        CVT2(w0, F0.y, F0.x); CVT2(w1, F0.w, F0.z);                            \
        CVT2(w2, F1.y, F1.x); CVT2(w3, F1.w, F1.z);                            \
        STS128(a_sts + (SOFF), w0, w1, w2, w3);                                \
    } while (0)

#define LOADB(KC, SOFF)                                                        \
    do {                                                                       \
        const char* _b = b_src + (size_t)(KC) * 64;                            \
        _Pragma("unroll")                                                      \
        for (int i = 0; i < 4; ++i)                                            \
            asm volatile("cp.async.cg.shared.global [%0], [%1], 16;"           \
                :: "r"(b_dst + (SOFF) + (uint32_t)i * 4096),                   \
                   "l"(_b + (size_t)i * 131072));                              \
    } while (0)

#define COMPUTE(SOFFA, SOFFB)                                                  \
    do {                                                                       \
        _Pragma("unroll")                                                      \
        for (int stk = 0; stk < 2; ++stk) {                                    \
            const uint32_t xr = (uint32_t)stk << 5;                            \
            uint32_t a0[4], a1[4];                                             \
            LDM4(a0[0], a0[1], a0[2], a0[3], (aAd[0] + (SOFFA)) ^ xr);         \
            LDM4(a1[0], a1[1], a1[2], a1[3], (aAd[1] + (SOFFA)) ^ xr);         \
            _Pragma("unroll")                                                  \
            for (int o = 0; o < 4; ++o) {                                      \
                uint32_t b0, b1, b2, b3;                                       \
                LDM4(b0, b1, b2, b3, (bAd[o] + (SOFFB)) ^ xr);                 \
                MMA_F16(acc[0][2 * o],     a0[0], a0[1], a0[2], a0[3], b0, b1);\
                MMA_F16(acc[1][2 * o],     a1[0], a1[1], a1[2], a1[3], b0, b1);\
                MMA_F16(acc[0][2 * o + 1], a0[0], a0[1], a0[2], a0[3], b2, b3);\
                MMA_F16(acc[1][2 * o + 1], a1[0], a1[1], a1[2], a1[3], b2, b3);\
            }                                                                  \
        }                                                                      \
    } while (0)

#define STG(K) ((uint32_t)((K) & 3))

    // ---------------- prologue ----------------
    LDGA_A(0); STSA_SET(aA0, aA1, 0u);          // chunk 0 -> A stage 0
    LDGA_A(1); STSA_SET(aA0, aA1, A_STAGE);     // chunk 1 -> A stage 1
    LOADB(0, 0u); LOADB(1, B_STAGE); CP_COMMIT();   // pair 0 = one group
    LDGA_A(2); LDGA_B(3);                       // A pair 1 in regs

    // ---------------- mainloop: 16 pairs, ONE sync + ONE wait per pair ----------------
#pragma unroll 1
    for (int p = 0; p < NCHUNKS / 2; ++p) {
        const int k2 = 2 * p + 2;
        CP_WAIT0();                              // B pair p fully arrived
        __syncthreads();                         // everyone done with pair p-1 stages
        if (k2 < NCHUNKS) {
            STSA_SET(aA0, aA1, STG(k2) * A_STAGE);
            STSA_SET(aB0, aB1, STG(k2 + 1) * A_STAGE);
            LOADB(k2,     STG(k2) * B_STAGE);
            LOADB(k2 + 1, STG(k2 + 1) * B_STAGE);
        }
        CP_COMMIT();                             // pair p+1 = one group (may be empty)
        if (k2 + 2 < NCHUNKS) { LDGA_A(k2 + 2); LDGA_B(k2 + 3); }
        COMPUTE(STG(2 * p) * A_STAGE,     STG(2 * p) * B_STAGE);
        COMPUTE(STG(2 * p + 1) * A_STAGE, STG(2 * p + 1) * B_STAGE);
    }

    // ---------------- LN1 finalize ----------------
    float* s1p = (float*)(smem + 4096);
    float* s2p = (float*)(smem + 5120);
    float* ca  = (float*)(smem + 6144);
    float* cb  = ca + 64;
    float* rowacc = (float*)(smem + SA_OFF);     // [64][4][2]
    float* mu2a = (float*)(smem + SA_OFF + 2048);
    float* rs2a = mu2a + 64;

    __syncthreads();
    s1p[tid] = s1; s2p[tid] = s2;
    __syncthreads();

    if (tid < 64) {
        float a = (s1p[tid * 4] + s1p[tid * 4 + 1]) + (s1p[tid * 4 + 2] + s1p[tid * 4 + 3]);
        float b = (s2p[tid * 4] + s2p[tid * 4 + 1]) + (s2p[tid * 4 + 2] + s2p[tid * 4 + 3]);
        float mu  = a * (1.0f / (float)D_MODEL);
        float var = fmaf(-mu, mu, b * (1.0f / (float)D_MODEL));
        float rs  = rsqrtf(var + EPS1);
        ca[tid] = rs;
        cb[tid] = -mu * rs;
    }
    rowacc[tid] = 0.f; rowacc[tid + 256] = 0.f;
    __syncthreads();

    // ---------------- h = ca*acc + cb*u + v; LN2 partial sums ----------------
#pragma unroll
    for (int mt = 0; mt < 2; ++mt) {
#pragma unroll
        for (int b = 0; b < 2; ++b) {
            int rr = wm * 32 + mt * 16 + qr + 8 * b;
            float cav = ca[rr], cbv = cb[rr];
            float t1 = 0.f, t2 = 0.f;
#pragma unroll
            for (int nt = 0; nt < 8; ++nt) {
                int p0 = wn * 64 + nt * 8 + 2 * qt;
                float h0 = fmaf(cav, acc[mt][nt][2 * b],     fmaf(cbv, suv[p0],     suv[256 + p0]));
                float h1 = fmaf(cav, acc[mt][nt][2 * b + 1], fmaf(cbv, suv[p0 + 1], suv[256 + p0 + 1]));
                acc[mt][nt][2 * b]     = h0;
                acc[mt][nt][2 * b + 1] = h1;
                t1 += h0 + h1;
                t2 += h0 * h0 + h1 * h1;
            }
            t1 += __shfl_xor_sync(0xFFFFFFFFu, t1, 1);
            t2 += __shfl_xor_sync(0xFFFFFFFFu, t2, 1);
            t1 += __shfl_xor_sync(0xFFFFFFFFu, t1, 2);
            t2 += __shfl_xor_sync(0xFFFFFFFFu, t2, 2);
            if (qt == 0) {
                rowacc[(rr * 4 + wn) * 2]     = t1;
                rowacc[(rr * 4 + wn) * 2 + 1] = t2;
            }
        }
    }
    __syncthreads();

    if (tid < 64) {
        float t1 = 0.f, t2 = 0.f;
#pragma unroll
        for (int w = 0; w < 4; ++w) {
            t1 += rowacc[(tid * 4 + w) * 2];
            t2 += rowacc[(tid * 4 + w) * 2 + 1];
        }
        float mu  = t1 * (1.0f / (float)D_PROJ);
        float var = fmaf(-mu, mu, t2 * (1.0f / (float)D_PROJ));
        mu2a[tid] = mu;
        rs2a[tid] = rsqrtf(var + EPS1);
    }
    __syncthreads();

    // ---------------- normalize + store ----------------
    float* outp = out + row0 * D_PROJ;
#pragma unroll
    for (int mt = 0; mt < 2; ++mt) {
#pragma unroll
        for (int b = 0; b < 2; ++b) {
            int rr = wm * 32 + mt * 16 + qr + 8 * b;
            float mu = mu2a[rr], rs = rs2a[rr];
#pragma unroll
            for (int nt = 0; nt < 8; ++nt) {
                int p0 = wn * 64 + nt * 8 + 2 * qt;
                float o0 = fmaf((acc[mt][nt][2 * b]     - mu) * rs, suv[512 + p0],     suv[768 + p0]);
                float o1 = fmaf((acc[mt][nt][2 * b + 1] - mu) * rs, suv[512 + p0 + 1], suv[768 + p0 + 1]);
                float2 o = make_float2(o0, o1);
                *(float2*)(outp + (size_t)rr * D_PROJ + p0) = o;
            }
        }
    }
#undef LDGA_A
#undef LDGA_B
#undef STSA_SET
#undef LOADB
#undef COMPUTE
#undef STG
}

// ---------------- launch ----------------
extern "C" void kernel_launch(void* const* d_in, const int* in_sizes, int n_in,
                              void* d_out, int out_size)
{
    const float* x    = (const float*)d_in[0];
    const float* g1   = (const float*)d_in[1];
    const float* b1   = (const float*)d_in[2];
    const float* W    = (const float*)d_in[3];
    const float* bias = (const float*)d_in[4];
    const float* g2   = (const float*)d_in[5];
    const float* b2   = (const float*)d_in[6];
    float* out = (float*)d_out;

    int n_tok = in_sizes[0] / D_MODEL;          // 65536
    int grid  = n_tok / MTILE;                  // 1024

    prep_kernel<<<D_PROJ, 256>>>(W, g1, b1, bias);

    cudaFuncSetAttribute(fused_kernel, cudaFuncAttributeMaxDynamicSharedMemorySize, SMEM_BYTES);
    fused_kernel<<<grid, 256, SMEM_BYTES>>>(x, g2, b2, out);
}